// round 13
// baseline (speedup 1.0000x reference)
#include <cuda_runtime.h>
#include <cuda_fp16.h>
#include <cstdint>
#include <math.h>

// Problem dims
#define LSEQ 2048
#define BATCH 8
#define DIM 1024
#define MROWS (LSEQ * BATCH)    // 16384
#define NCOLS (3 * DIM)         // 3072
#define LN_EPS 1e-5f
#define KB 1024

// GEMM tiling
#define BM 128
#define BN 192
#define BK 64
#define NCH (KB / BK)           // 16
#define STG 4
#define NTN (NCOLS / BN)        // 16
#define NTILE (NTN * (MROWS / BM))   // 2048

// Scan chunking
#define SCH 32
#define SCL (LSEQ / SCH)        // 64

// Scratch
__device__ __align__(128) __half g_ah[(size_t)MROWS * DIM];     // 32 MB
__device__ __align__(128) __half g_bext[(size_t)NCOLS * KB];    // 6 MB
__device__ __align__(128) __half g_ufr[(size_t)MROWS * NCOLS];  // 96 MB
__device__ float g_mu[MROWS];
__device__ float g_rs[MROWS];
__device__ float g_P  [SCH * BATCH * DIM];
__device__ float g_q  [SCH * BATCH * DIM];
__device__ float g_cin[SCH * BATCH * DIM];

// ---------------------------------------------------------------------------
__device__ __forceinline__ float htanh(float x) {      // HW MUFU tanh
    float y; asm("tanh.approx.f32 %0, %1;" : "=f"(y) : "f"(x)); return y;
}
__device__ __forceinline__ float hsigmoid(float x) {
    return fmaf(0.5f, htanh(0.5f * x), 0.5f);
}

// ---------------------------------------------------------------------------
// Kernel 1 (merged): LN warp-per-row -> fp16 + stats; W -> fp16
// ---------------------------------------------------------------------------
#define LNB (MROWS / 8)         // 2048 LN blocks

__global__ void __launch_bounds__(256) sru_prep(const float* __restrict__ x,
                                                const float* __restrict__ ln_g,
                                                const float* __restrict__ ln_b,
                                                const float* __restrict__ W) {
    const int t = threadIdx.x;

    if (blockIdx.x < LNB) {
        const int warp = t >> 5;
        const int lane = t & 31;
        const int row = blockIdx.x * 8 + warp;

        float4 a[8];
        float s = 0.f, ss = 0.f;
        #pragma unroll
        for (int i = 0; i < 8; i++) {
            a[i] = ((const float4*)(x + (size_t)row * DIM))[lane + i * 32];
            s  += a[i].x + a[i].y + a[i].z + a[i].w;
            ss += a[i].x * a[i].x + a[i].y * a[i].y
                + a[i].z * a[i].z + a[i].w * a[i].w;
        }
        #pragma unroll
        for (int o = 16; o > 0; o >>= 1) {
            s  += __shfl_xor_sync(0xFFFFFFFFu, s, o);
            ss += __shfl_xor_sync(0xFFFFFFFFu, ss, o);
        }
        const float mu   = s * (1.0f / DIM);
        const float var  = ss * (1.0f / DIM) - mu * mu;
        const float rstd = rsqrtf(var + LN_EPS);
        if (lane == 0) { g_mu[row] = mu; g_rs[row] = rstd; }

        #pragma unroll
        for (int i = 0; i < 8; i++) {
            const float4 g = ((const float4*)ln_g)[lane + i * 32];
            const float4 b = ((const float4*)ln_b)[lane + i * 32];
            float o[4];
            o[0] = (a[i].x - mu) * rstd * g.x + b.x;
            o[1] = (a[i].y - mu) * rstd * g.y + b.y;
            o[2] = (a[i].z - mu) * rstd * g.z + b.z;
            o[3] = (a[i].w - mu) * rstd * g.w + b.w;
            union { __half v[4]; uint2 u; } H;
            #pragma unroll
            for (int e = 0; e < 4; e++) H.v[e] = __float2half_rn(o[e]);
            ((uint2*)(g_ah + (size_t)row * DIM))[lane + i * 32] = H.u;
        }
    } else {
        const int row = blockIdx.x - LNB;
        const int c4  = t;
        float4 v = ((const float4*)(W + (size_t)row * DIM))[c4];
        float o[4] = {v.x, v.y, v.z, v.w};
        union { __half v[4]; uint2 u2; } H;
        #pragma unroll
        for (int i = 0; i < 4; i++) H.v[i] = __float2half_rn(o[i]);
        ((uint2*)(g_bext + (size_t)row * KB))[c4] = H.u2;
    }
}

// ---------------------------------------------------------------------------
// Kernel 2: persistent HMMA GEMM, BM=128 x BN=192, continuous cp.async stream.
// ---------------------------------------------------------------------------
#define ASTG_BYTES (BM * 128)
#define BSTG_BYTES (BN * 128)
#define STG_BYTES  (ASTG_BYTES + BSTG_BYTES)   // 40 KB
#define SMEM_GEMM  (STG * STG_BYTES)           // 160 KB

__device__ __forceinline__ void cp_async16(uint32_t dst, const void* src) {
    asm volatile("cp.async.cg.shared.global [%0], [%1], 16;" :: "r"(dst), "l"(src));
}
__device__ __forceinline__ void ldsm_x4(uint32_t& r0, uint32_t& r1, uint32_t& r2,
                                        uint32_t& r3, uint32_t addr) {
    asm volatile("ldmatrix.sync.aligned.m8n8.x4.shared.b16 {%0,%1,%2,%3}, [%4];"
                 : "=r"(r0), "=r"(r1), "=r"(r2), "=r"(r3) : "r"(addr));
}
__device__ __forceinline__ void mma16816(float* d, const uint32_t* a,
                                         const uint32_t* b) {
    asm volatile(
        "mma.sync.aligned.m16n8k16.row.col.f32.f16.f16.f32 "
        "{%0,%1,%2,%3}, {%4,%5,%6,%7}, {%8,%9}, {%0,%1,%2,%3};"
        : "+f"(d[0]), "+f"(d[1]), "+f"(d[2]), "+f"(d[3])
        : "r"(a[0]), "r"(a[1]), "r"(a[2]), "r"(a[3]), "r"(b[0]), "r"(b[1]));
}

__global__ void __launch_bounds__(256, 1) sru_gemm_hmma(const float* __restrict__ bias) {
    extern __shared__ char smem[];
    const uint32_t sbase = (uint32_t)__cvta_generic_to_shared(smem);
    const int tid  = threadIdx.x;
    const int lane = tid & 31;
    const int warp = tid >> 5;
    const int wm   = (warp >> 2) * 64;
    const int wn   = (warp & 3) * 48;

    auto load_stage = [&](int ltile, int lc, int buf) {
        const int lbm = (ltile >> 4) * BM;
        const int lbn = (ltile & 15) * BN;
        const uint32_t sA = sbase + buf * STG_BYTES;
        const uint32_t sB = sA + ASTG_BYTES;
        #pragma unroll
        for (int i = 0; i < 4; i++) {
            const int u = tid + i * 256;
            const int r = u >> 3, j = u & 7;
            const __half* src = g_ah + (size_t)(lbm + r) * DIM + lc * BK + j * 8;
            cp_async16(sA + r * 128 + ((j ^ (r & 7)) << 4), src);
        }
        #pragma unroll
        for (int i = 0; i < 6; i++) {
            const int u = tid + i * 256;
            const int r = u >> 3, j = u & 7;
            const __half* src = g_bext + (size_t)(lbn + r) * KB + lc * BK + j * 8;
            cp_async16(sB + r * 128 + ((j ^ (r & 7)) << 4), src);
        }
    };

    const int grid = gridDim.x;
    int tile = blockIdx.x;

    #pragma unroll
    for (int s = 0; s < 3; s++) {
        load_stage(tile, s, s);
        asm volatile("cp.async.commit_group;");
    }

    const int aRow = ((lane >> 3) & 1) * 8 + (lane & 7);
    const int aJ   = (lane >> 4);
    const int bRow = ((lane >> 4) & 1) * 8 + (lane & 7);
    const int bJ   = (lane >> 3) & 1;

    for (; tile < NTILE; tile += grid) {
        const int bm = (tile >> 4) * BM;
        const int bn = (tile & 15) * BN;

        float acc[4][6][4];
        #pragma unroll
        for (int i = 0; i < 4; i++)
            #pragma unroll
            for (int j = 0; j < 6; j++)
                #pragma unroll
                for (int e = 0; e < 4; e++) acc[i][j][e] = 0.0f;

        for (int c = 0; c < NCH; c++) {
            asm volatile("cp.async.wait_group 2;");
            __syncthreads();

            {
                int lt = tile, lc = c + 3;
                if (lc >= NCH) { lt = tile + grid; lc -= NCH; }
                if (lt < NTILE) load_stage(lt, lc, (c + 3) & 3);
            }
            asm volatile("cp.async.commit_group;");

            const int buf = c & 3;
            const uint32_t sA = sbase + buf * STG_BYTES;
            const uint32_t sB = sA + ASTG_BYTES;

            #pragma unroll
            for (int s = 0; s < 4; s++) {
                uint32_t af[4][4];
                #pragma unroll
                for (int i = 0; i < 4; i++) {
                    const int r = wm + i * 16 + aRow;
                    const int j = 2 * s + aJ;
                    ldsm_x4(af[i][0], af[i][1], af[i][2], af[i][3],
                            sA + r * 128 + ((j ^ (r & 7)) << 4));
                }
                uint32_t bf[3][4];
                #pragma unroll
                for (int p = 0; p < 3; p++) {
                    const int r = wn + p * 16 + bRow;
                    const int j = 2 * s + bJ;
                    ldsm_x4(bf[p][0], bf[p][1], bf[p][2], bf[p][3],
                            sB + r * 128 + ((j ^ (r & 7)) << 4));
                }
                #pragma unroll
                for (int i = 0; i < 4; i++)
                    #pragma unroll
                    for (int p = 0; p < 3; p++) {
                        mma16816(acc[i][2 * p],     af[i], &bf[p][0]);
                        mma16816(acc[i][2 * p + 1], af[i], &bf[p][2]);
                    }
            }
        }

        const int mrow0 = bm + wm + (lane >> 2);
        const int ncol0 = bn + wn + 2 * (lane & 3);
        #pragma unroll
        for (int j = 0; j < 6; j++) {
            const int nb = bn + wn + j * 8;
            const int n  = ncol0 + j * 8;
            const float2 b2 = *(const float2*)&bias[n];
            const bool is_u = (nb < DIM);
            #pragma unroll
            for (int i = 0; i < 4; i++) {
                const int m0 = mrow0 + i * 16;
                float v0 = acc[i][j][0] + b2.x;
                float v1 = acc[i][j][1] + b2.y;
                float v2 = acc[i][j][2] + b2.x;
                float v3 = acc[i][j][3] + b2.y;
                float2 o0, o1;
                if (is_u) { o0 = {htanh(v0), htanh(v1)};       o1 = {htanh(v2), htanh(v3)}; }
                else      { o0 = {hsigmoid(v0), hsigmoid(v1)}; o1 = {hsigmoid(v2), hsigmoid(v3)}; }
                *(__half2*)&g_ufr[(size_t)m0 * NCOLS + n]       = __floats2half2_rn(o0.x, o0.y);
                *(__half2*)&g_ufr[(size_t)(m0 + 8) * NCOLS + n] = __floats2half2_rn(o1.x, o1.y);
            }
        }
    }
}

// ---------------------------------------------------------------------------
// Kernel 3a: per-chunk (P, q); 4 lanes of d per thread (uint2 of half2)
// ---------------------------------------------------------------------------
__global__ void __launch_bounds__(256) sru_scanA() {
    const int idx = blockIdx.x * 256 + threadIdx.x;   // 0..65535
    const int chunk = idx >> 11;
    const int r     = idx & 2047;
    const int b     = r >> 8;
    const int dq    = r & 255;            // 4-elem index; d = 4*dq
    const int m0 = chunk * SCL * BATCH + b;

    float P[4] = {1.f, 1.f, 1.f, 1.f};
    float q[4] = {0.f, 0.f, 0.f, 0.f};
    #pragma unroll 4
    for (int s = 0; s < SCL; s++) {
        const size_t m = (size_t)(m0 + s * BATCH);
        const __half* row = g_ufr + m * NCOLS;
        union { uint2 w; __half2 h[2]; } uu, ff;
        uu.w = ((const uint2*)row)[dq];
        ff.w = ((const uint2*)(row + DIM))[dq];
        #pragma unroll
        for (int e = 0; e < 2; e++) {
            const float2 u2 = __half22float2(uu.h[e]);
            const float2 f2 = __half22float2(ff.h[e]);
            q[2*e]   = f2.x * q[2*e]   + (1.0f - f2.x) * u2.x;
            q[2*e+1] = f2.y * q[2*e+1] + (1.0f - f2.y) * u2.y;
            P[2*e]   *= f2.x;
            P[2*e+1] *= f2.y;
        }
    }
    const int o = chunk * 8192 + b * DIM + 4 * dq;
    *(float4*)&g_P[o] = *(float4*)P;
    *(float4*)&g_q[o] = *(float4*)q;
}

// ---------------------------------------------------------------------------
// Kernel 3b: serial chunk combine — fully unrolled, loads front-batched
// ---------------------------------------------------------------------------
__global__ void __launch_bounds__(256) sru_scanB(const float* __restrict__ c0,
                                                 float* __restrict__ out) {
    const int idx = blockIdx.x * 256 + threadIdx.x;   // 0..8191
    float P[SCH], q[SCH];
    #pragma unroll
    for (int k = 0; k < SCH; k++) {
        P[k] = g_P[k * 8192 + idx];
        q[k] = g_q[k * 8192 + idx];
    }
    float c = c0[idx];
    #pragma unroll
    for (int k = 0; k < SCH; k++) {
        g_cin[k * 8192 + idx] = c;
        c = P[k] * c + q[k];
    }
    out[(size_t)MROWS * DIM + idx] = c;
}

// ---------------------------------------------------------------------------
// Kernel 3c: re-scan with true c_in (4-wide); xn from (x, mu, rstd); MUFU tanh
// ---------------------------------------------------------------------------
__global__ void __launch_bounds__(256) sru_scanC(const float* __restrict__ x,
                                                 const float* __restrict__ ln_g,
                                                 const float* __restrict__ ln_b,
                                                 float* __restrict__ out) {
    const int idx = blockIdx.x * 256 + threadIdx.x;   // 0..65535
    const int chunk = idx >> 11;
    const int r     = idx & 2047;
    const int b     = r >> 8;
    const int dq    = r & 255;
    const int m0 = chunk * SCL * BATCH + b;

    const float4 lg = ((const float4*)ln_g)[dq];
    const float4 lb = ((const float4*)ln_b)[dq];
    const float lgv[4] = {lg.x, lg.y, lg.z, lg.w};
    const float lbv[4] = {lb.x, lb.y, lb.z, lb.w};

    float c[4];
    *(float4*)c = *(const float4*)&g_cin[chunk * 8192 + b * DIM + 4 * dq];
    #pragma unroll 4
    for (int s = 0; s < SCL; s++) {
        const size_t m = (size_t)(m0 + s * BATCH);
        const __half* row = g_ufr + m * NCOLS;
        union { uint2 w; __half2 h[2]; } uu, ff, rr;
        uu.w = ((const uint2*)row)[dq];
        ff.w = ((const uint2*)(row + DIM))[dq];
        rr.w = ((const uint2*)(row + 2 * DIM))[dq];
        const float4 xv = ((const float4*)(x + m * DIM))[dq];
        const float mu = g_mu[m];
        const float rs = g_rs[m];
        const float xvv[4] = {xv.x, xv.y, xv.z, xv.w};
        float o[4];
        #pragma unroll
        for (int e = 0; e < 2; e++) {
            const float2 u2 = __half22float2(uu.h[e]);
            const float2 f2 = __half22float2(ff.h[e]);
            const float2 r2 = __half22float2(rr.h[e]);
            const float uu4[2] = {u2.x, u2.y};
            const float ff4[2] = {f2.x, f2.y};
            const float rr4[2] = {r2.x, r2.y};
            #pragma unroll
            for (int w = 0; w < 2; w++) {
                const int k = 2 * e + w;
                const float xn = (xvv[k] - mu) * rs * lgv[k] + lbv[k];
                c[k] = ff4[w] * c[k] + (1.0f - ff4[w]) * uu4[w];
                o[k] = xvv[k] + rr4[w] * htanh(c[k]) + (1.0f - rr4[w]) * xn;
            }
        }
        ((float4*)(out + m * DIM))[dq] = *(float4*)o;
    }
}

// ---------------------------------------------------------------------------
extern "C" void kernel_launch(void* const* d_in, const int* in_sizes, int n_in,
                              void* d_out, int out_size) {
    const float* x    = (const float*)d_in[0];
    const float* c    = (const float*)d_in[1];
    const float* W    = (const float*)d_in[2];
    const float* b    = (const float*)d_in[3];
    const float* ln_g = (const float*)d_in[4];
    const float* ln_b = (const float*)d_in[5];
    float* out = (float*)d_out;

    cudaFuncSetAttribute(sru_gemm_hmma, cudaFuncAttributeMaxDynamicSharedMemorySize,
                         SMEM_GEMM);

    int nsm = 148;
    cudaDeviceGetAttribute(&nsm, cudaDevAttrMultiProcessorCount, 0);
    if (nsm <= 0 || nsm > NTILE) nsm = 148;

    sru_prep<<<LNB + NCOLS, 256>>>(x, ln_g, ln_b, W);

    sru_gemm_hmma<<<nsm, 256, SMEM_GEMM>>>(b);

    sru_scanA<<<(SCH * BATCH * DIM / 4) / 256, 256>>>();
    sru_scanB<<<(BATCH * DIM) / 256, 256>>>(c, out);
    sru_scanC<<<(SCH * BATCH * DIM / 4) / 256, 256>>>(x, ln_g, ln_b, out);
}

// round 14
// speedup vs baseline: 1.0305x; 1.0305x over previous
#include <cuda_runtime.h>
#include <cuda_fp16.h>
#include <cstdint>
#include <math.h>

// Problem dims
#define LSEQ 2048
#define BATCH 8
#define DIM 1024
#define MROWS (LSEQ * BATCH)    // 16384
#define NCOLS (3 * DIM)         // 3072
#define LN_EPS 1e-5f
#define KB 1024

// GEMM tiling
#define BM 128
#define BN 192
#define BK 64
#define NCH (KB / BK)           // 16
#define STG 4
#define NTN (NCOLS / BN)        // 16
#define NTILE (NTN * (MROWS / BM))   // 2048

// Scan chunking
#define SCH 32
#define SCL (LSEQ / SCH)        // 64

// Scratch
__device__ __align__(128) __half g_ah[(size_t)MROWS * DIM];     // 32 MB
__device__ __align__(128) __half g_bext[(size_t)NCOLS * KB];    // 6 MB
__device__ __align__(128) __half g_ufr[(size_t)MROWS * NCOLS];  // 96 MB
__device__ float g_mu[MROWS];
__device__ float g_rs[MROWS];
__device__ float g_P  [SCH * BATCH * DIM];
__device__ float g_q  [SCH * BATCH * DIM];
__device__ float g_cin[SCH * BATCH * DIM];

// ---------------------------------------------------------------------------
__device__ __forceinline__ float htanh(float x) {      // HW MUFU tanh
    float y; asm("tanh.approx.f32 %0, %1;" : "=f"(y) : "f"(x)); return y;
}
__device__ __forceinline__ float hsigmoid(float x) {
    return fmaf(0.5f, htanh(0.5f * x), 0.5f);
}

// ---------------------------------------------------------------------------
// Kernel 1 (merged): LN warp-per-row -> fp16 + stats; W -> fp16
// ---------------------------------------------------------------------------
#define LNB (MROWS / 8)         // 2048 LN blocks

__global__ void __launch_bounds__(256) sru_prep(const float* __restrict__ x,
                                                const float* __restrict__ ln_g,
                                                const float* __restrict__ ln_b,
                                                const float* __restrict__ W) {
    const int t = threadIdx.x;

    if (blockIdx.x < LNB) {
        const int warp = t >> 5;
        const int lane = t & 31;
        const int row = blockIdx.x * 8 + warp;

        float4 a[8];
        float s = 0.f, ss = 0.f;
        #pragma unroll
        for (int i = 0; i < 8; i++) {
            a[i] = ((const float4*)(x + (size_t)row * DIM))[lane + i * 32];
            s  += a[i].x + a[i].y + a[i].z + a[i].w;
            ss += a[i].x * a[i].x + a[i].y * a[i].y
                + a[i].z * a[i].z + a[i].w * a[i].w;
        }
        #pragma unroll
        for (int o = 16; o > 0; o >>= 1) {
            s  += __shfl_xor_sync(0xFFFFFFFFu, s, o);
            ss += __shfl_xor_sync(0xFFFFFFFFu, ss, o);
        }
        const float mu   = s * (1.0f / DIM);
        const float var  = ss * (1.0f / DIM) - mu * mu;
        const float rstd = rsqrtf(var + LN_EPS);
        if (lane == 0) { g_mu[row] = mu; g_rs[row] = rstd; }

        #pragma unroll
        for (int i = 0; i < 8; i++) {
            const float4 g = ((const float4*)ln_g)[lane + i * 32];
            const float4 b = ((const float4*)ln_b)[lane + i * 32];
            float o[4];
            o[0] = (a[i].x - mu) * rstd * g.x + b.x;
            o[1] = (a[i].y - mu) * rstd * g.y + b.y;
            o[2] = (a[i].z - mu) * rstd * g.z + b.z;
            o[3] = (a[i].w - mu) * rstd * g.w + b.w;
            union { __half v[4]; uint2 u; } H;
            #pragma unroll
            for (int e = 0; e < 4; e++) H.v[e] = __float2half_rn(o[e]);
            ((uint2*)(g_ah + (size_t)row * DIM))[lane + i * 32] = H.u;
        }
    } else {
        const int row = blockIdx.x - LNB;
        const int c4  = t;
        float4 v = ((const float4*)(W + (size_t)row * DIM))[c4];
        float o[4] = {v.x, v.y, v.z, v.w};
        union { __half v[4]; uint2 u2; } H;
        #pragma unroll
        for (int i = 0; i < 4; i++) H.v[i] = __float2half_rn(o[i]);
        ((uint2*)(g_bext + (size_t)row * KB))[c4] = H.u2;
    }
}

// ---------------------------------------------------------------------------
// Kernel 2: persistent HMMA GEMM, BM=128 x BN=192, continuous cp.async stream.
// ---------------------------------------------------------------------------
#define ASTG_BYTES (BM * 128)
#define BSTG_BYTES (BN * 128)
#define STG_BYTES  (ASTG_BYTES + BSTG_BYTES)   // 40 KB
#define SMEM_GEMM  (STG * STG_BYTES)           // 160 KB

__device__ __forceinline__ void cp_async16(uint32_t dst, const void* src) {
    asm volatile("cp.async.cg.shared.global [%0], [%1], 16;" :: "r"(dst), "l"(src));
}
__device__ __forceinline__ void ldsm_x4(uint32_t& r0, uint32_t& r1, uint32_t& r2,
                                        uint32_t& r3, uint32_t addr) {
    asm volatile("ldmatrix.sync.aligned.m8n8.x4.shared.b16 {%0,%1,%2,%3}, [%4];"
                 : "=r"(r0), "=r"(r1), "=r"(r2), "=r"(r3) : "r"(addr));
}
__device__ __forceinline__ void mma16816(float* d, const uint32_t* a,
                                         const uint32_t* b) {
    asm volatile(
        "mma.sync.aligned.m16n8k16.row.col.f32.f16.f16.f32 "
        "{%0,%1,%2,%3}, {%4,%5,%6,%7}, {%8,%9}, {%0,%1,%2,%3};"
        : "+f"(d[0]), "+f"(d[1]), "+f"(d[2]), "+f"(d[3])
        : "r"(a[0]), "r"(a[1]), "r"(a[2]), "r"(a[3]), "r"(b[0]), "r"(b[1]));
}

__global__ void __launch_bounds__(256, 1) sru_gemm_hmma(const float* __restrict__ bias) {
    extern __shared__ char smem[];
    const uint32_t sbase = (uint32_t)__cvta_generic_to_shared(smem);
    const int tid  = threadIdx.x;
    const int lane = tid & 31;
    const int warp = tid >> 5;
    const int wm   = (warp >> 2) * 64;
    const int wn   = (warp & 3) * 48;

    auto load_stage = [&](int ltile, int lc, int buf) {
        const int lbm = (ltile >> 4) * BM;
        const int lbn = (ltile & 15) * BN;
        const uint32_t sA = sbase + buf * STG_BYTES;
        const uint32_t sB = sA + ASTG_BYTES;
        #pragma unroll
        for (int i = 0; i < 4; i++) {
            const int u = tid + i * 256;
            const int r = u >> 3, j = u & 7;
            const __half* src = g_ah + (size_t)(lbm + r) * DIM + lc * BK + j * 8;
            cp_async16(sA + r * 128 + ((j ^ (r & 7)) << 4), src);
        }
        #pragma unroll
        for (int i = 0; i < 6; i++) {
            const int u = tid + i * 256;
            const int r = u >> 3, j = u & 7;
            const __half* src = g_bext + (size_t)(lbn + r) * KB + lc * BK + j * 8;
            cp_async16(sB + r * 128 + ((j ^ (r & 7)) << 4), src);
        }
    };

    const int grid = gridDim.x;
    int tile = blockIdx.x;

    #pragma unroll
    for (int s = 0; s < 3; s++) {
        load_stage(tile, s, s);
        asm volatile("cp.async.commit_group;");
    }

    const int aRow = ((lane >> 3) & 1) * 8 + (lane & 7);
    const int aJ   = (lane >> 4);
    const int bRow = ((lane >> 4) & 1) * 8 + (lane & 7);
    const int bJ   = (lane >> 3) & 1;

    for (; tile < NTILE; tile += grid) {
        const int bm = (tile >> 4) * BM;
        const int bn = (tile & 15) * BN;

        float acc[4][6][4];
        #pragma unroll
        for (int i = 0; i < 4; i++)
            #pragma unroll
            for (int j = 0; j < 6; j++)
                #pragma unroll
                for (int e = 0; e < 4; e++) acc[i][j][e] = 0.0f;

        for (int c = 0; c < NCH; c++) {
            asm volatile("cp.async.wait_group 2;");
            __syncthreads();

            {
                int lt = tile, lc = c + 3;
                if (lc >= NCH) { lt = tile + grid; lc -= NCH; }
                if (lt < NTILE) load_stage(lt, lc, (c + 3) & 3);
            }
            asm volatile("cp.async.commit_group;");

            const int buf = c & 3;
            const uint32_t sA = sbase + buf * STG_BYTES;
            const uint32_t sB = sA + ASTG_BYTES;

            #pragma unroll
            for (int s = 0; s < 4; s++) {
                uint32_t af[4][4];
                #pragma unroll
                for (int i = 0; i < 4; i++) {
                    const int r = wm + i * 16 + aRow;
                    const int j = 2 * s + aJ;
                    ldsm_x4(af[i][0], af[i][1], af[i][2], af[i][3],
                            sA + r * 128 + ((j ^ (r & 7)) << 4));
                }
                uint32_t bf[3][4];
                #pragma unroll
                for (int p = 0; p < 3; p++) {
                    const int r = wn + p * 16 + bRow;
                    const int j = 2 * s + bJ;
                    ldsm_x4(bf[p][0], bf[p][1], bf[p][2], bf[p][3],
                            sB + r * 128 + ((j ^ (r & 7)) << 4));
                }
                #pragma unroll
                for (int i = 0; i < 4; i++)
                    #pragma unroll
                    for (int p = 0; p < 3; p++) {
                        mma16816(acc[i][2 * p],     af[i], &bf[p][0]);
                        mma16816(acc[i][2 * p + 1], af[i], &bf[p][2]);
                    }
            }
        }

        const int mrow0 = bm + wm + (lane >> 2);
        const int ncol0 = bn + wn + 2 * (lane & 3);
        #pragma unroll
        for (int j = 0; j < 6; j++) {
            const int nb = bn + wn + j * 8;
            const int n  = ncol0 + j * 8;
            const float2 b2 = *(const float2*)&bias[n];
            const bool is_u = (nb < DIM);
            #pragma unroll
            for (int i = 0; i < 4; i++) {
                const int m0 = mrow0 + i * 16;
                float v0 = acc[i][j][0] + b2.x;
                float v1 = acc[i][j][1] + b2.y;
                float v2 = acc[i][j][2] + b2.x;
                float v3 = acc[i][j][3] + b2.y;
                float2 o0, o1;
                if (is_u) { o0 = {htanh(v0), htanh(v1)};       o1 = {htanh(v2), htanh(v3)}; }
                else      { o0 = {hsigmoid(v0), hsigmoid(v1)}; o1 = {hsigmoid(v2), hsigmoid(v3)}; }
                *(__half2*)&g_ufr[(size_t)m0 * NCOLS + n]       = __floats2half2_rn(o0.x, o0.y);
                *(__half2*)&g_ufr[(size_t)(m0 + 8) * NCOLS + n] = __floats2half2_rn(o1.x, o1.y);
            }
        }
    }
}

// ---------------------------------------------------------------------------
// Kernel 3a: per-chunk (P, q); 2 lanes of d per thread (half2)
// ---------------------------------------------------------------------------
__global__ void __launch_bounds__(256) sru_scanA() {
    const int idx = blockIdx.x * 256 + threadIdx.x;   // 0..131071
    const int chunk = idx >> 12;
    const int r     = idx & 4095;
    const int b     = r >> 9;
    const int dh    = r & 511;
    const int m0 = chunk * SCL * BATCH + b;

    float2 P = {1.0f, 1.0f}, q = {0.0f, 0.0f};
    #pragma unroll 4
    for (int s = 0; s < SCL; s++) {
        const size_t m = (size_t)(m0 + s * BATCH);
        const __half2* row = (const __half2*)(g_ufr + m * NCOLS);
        const float2 u = __half22float2(row[dh]);
        const float2 f = __half22float2(row[dh + DIM / 2]);
        q.x = f.x * q.x + (1.0f - f.x) * u.x;
        q.y = f.y * q.y + (1.0f - f.y) * u.y;
        P.x *= f.x;
        P.y *= f.y;
    }
    const int o = chunk * 8192 + b * DIM + 2 * dh;
    *(float2*)&g_P[o] = P;
    *(float2*)&g_q[o] = q;
}

// ---------------------------------------------------------------------------
// Kernel 3b: serial chunk combine — fully unrolled, loads front-batched
// ---------------------------------------------------------------------------
__global__ void __launch_bounds__(256) sru_scanB(const float* __restrict__ c0,
                                                 float* __restrict__ out) {
    const int idx = blockIdx.x * 256 + threadIdx.x;   // 0..8191
    float P[SCH], q[SCH];
    #pragma unroll
    for (int k = 0; k < SCH; k++) {
        P[k] = g_P[k * 8192 + idx];
        q[k] = g_q[k * 8192 + idx];
    }
    float c = c0[idx];
    #pragma unroll
    for (int k = 0; k < SCH; k++) {
        g_cin[k * 8192 + idx] = c;
        c = P[k] * c + q[k];
    }
    out[(size_t)MROWS * DIM + idx] = c;
}

// ---------------------------------------------------------------------------
// Kernel 3c: re-scan with true c_in (2-wide); xn from (x, mu, rstd); MUFU tanh
// ---------------------------------------------------------------------------
__global__ void __launch_bounds__(256) sru_scanC(const float* __restrict__ x,
                                                 const float* __restrict__ ln_g,
                                                 const float* __restrict__ ln_b,
                                                 float* __restrict__ out) {
    const int idx = blockIdx.x * 256 + threadIdx.x;
    const int chunk = idx >> 12;
    const int r     = idx & 4095;
    const int b     = r >> 9;
    const int dh    = r & 511;
    const int m0 = chunk * SCL * BATCH + b;

    const float2 lg = ((const float2*)ln_g)[dh];
    const float2 lb = ((const float2*)ln_b)[dh];

    float2 c = *(const float2*)&g_cin[chunk * 8192 + b * DIM + 2 * dh];
    #pragma unroll 4
    for (int s = 0; s < SCL; s++) {
        const size_t m = (size_t)(m0 + s * BATCH);
        const __half2* row = (const __half2*)(g_ufr + m * NCOLS);
        const float2 u  = __half22float2(row[dh]);
        const float2 f  = __half22float2(row[dh + DIM / 2]);
        const float2 rg = __half22float2(row[dh + DIM]);
        const float2 xv = ((const float2*)(x + m * DIM))[dh];
        const float mu = g_mu[m];
        const float rs = g_rs[m];
        const float2 xn = {(xv.x - mu) * rs * lg.x + lb.x,
                           (xv.y - mu) * rs * lg.y + lb.y};
        c.x = f.x * c.x + (1.0f - f.x) * u.x;
        c.y = f.y * c.y + (1.0f - f.y) * u.y;
        float2 o;
        o.x = xv.x + rg.x * htanh(c.x) + (1.0f - rg.x) * xn.x;
        o.y = xv.y + rg.y * htanh(c.y) + (1.0f - rg.y) * xn.y;
        ((float2*)(out + m * DIM))[dh] = o;
    }
}

// ---------------------------------------------------------------------------
extern "C" void kernel_launch(void* const* d_in, const int* in_sizes, int n_in,
                              void* d_out, int out_size) {
    const float* x    = (const float*)d_in[0];
    const float* c    = (const float*)d_in[1];
    const float* W    = (const float*)d_in[2];
    const float* b    = (const float*)d_in[3];
    const float* ln_g = (const float*)d_in[4];
    const float* ln_b = (const float*)d_in[5];
    float* out = (float*)d_out;

    cudaFuncSetAttribute(sru_gemm_hmma, cudaFuncAttributeMaxDynamicSharedMemorySize,
                         SMEM_GEMM);

    int nsm = 148;
    cudaDeviceGetAttribute(&nsm, cudaDevAttrMultiProcessorCount, 0);
    if (nsm <= 0 || nsm > NTILE) nsm = 148;

    sru_prep<<<LNB + NCOLS, 256>>>(x, ln_g, ln_b, W);

    sru_gemm_hmma<<<nsm, 256, SMEM_GEMM>>>(b);

    sru_scanA<<<(SCH * BATCH * DIM / 2) / 256, 256>>>();
    sru_scanB<<<(BATCH * DIM) / 256, 256>>>(c, out);
    sru_scanC<<<(SCH * BATCH * DIM / 2) / 256, 256>>>(x, ln_g, ln_b, out);
}

// round 15
// speedup vs baseline: 1.0739x; 1.0422x over previous
#include <cuda_runtime.h>
#include <cuda_fp16.h>
#include <cstdint>
#include <math.h>

// Problem dims
#define LSEQ 2048
#define BATCH 8
#define DIM 1024
#define MROWS (LSEQ * BATCH)    // 16384
#define NCOLS (3 * DIM)         // 3072
#define LN_EPS 1e-5f
#define KB 1024

// GEMM tiling
#define BM 128
#define BN 192
#define BK 64
#define NCH (KB / BK)           // 16
#define STG 4
#define NTN (NCOLS / BN)        // 16
#define NTILE (NTN * (MROWS / BM))   // 2048

// Scan chunking
#define SCH 64
#define SCL (LSEQ / SCH)        // 32

// Scratch
__device__ __align__(128) __half g_ah[(size_t)MROWS * DIM];     // 32 MB
__device__ __align__(128) __half g_bext[(size_t)NCOLS * KB];    // 6 MB
__device__ __align__(128) __half g_ufr[(size_t)MROWS * NCOLS];  // 96 MB
__device__ float g_mu[MROWS];
__device__ float g_rs[MROWS];
__device__ float g_P  [SCH * BATCH * DIM];   // 2 MB
__device__ float g_q  [SCH * BATCH * DIM];   // 2 MB
__device__ float g_cin[SCH * BATCH * DIM];   // 2 MB

// ---------------------------------------------------------------------------
__device__ __forceinline__ float htanh(float x) {      // HW MUFU tanh
    float y; asm("tanh.approx.f32 %0, %1;" : "=f"(y) : "f"(x)); return y;
}
__device__ __forceinline__ float hsigmoid(float x) {
    return fmaf(0.5f, htanh(0.5f * x), 0.5f);
}

// ---------------------------------------------------------------------------
// Kernel 1 (merged): LN warp-per-row -> fp16 + stats; W -> fp16
// ---------------------------------------------------------------------------
#define LNB (MROWS / 8)         // 2048 LN blocks

__global__ void __launch_bounds__(256) sru_prep(const float* __restrict__ x,
                                                const float* __restrict__ ln_g,
                                                const float* __restrict__ ln_b,
                                                const float* __restrict__ W) {
    const int t = threadIdx.x;

    if (blockIdx.x < LNB) {
        const int warp = t >> 5;
        const int lane = t & 31;
        const int row = blockIdx.x * 8 + warp;

        float4 a[8];
        float s = 0.f, ss = 0.f;
        #pragma unroll
        for (int i = 0; i < 8; i++) {
            a[i] = ((const float4*)(x + (size_t)row * DIM))[lane + i * 32];
            s  += a[i].x + a[i].y + a[i].z + a[i].w;
            ss += a[i].x * a[i].x + a[i].y * a[i].y
                + a[i].z * a[i].z + a[i].w * a[i].w;
        }
        #pragma unroll
        for (int o = 16; o > 0; o >>= 1) {
            s  += __shfl_xor_sync(0xFFFFFFFFu, s, o);
            ss += __shfl_xor_sync(0xFFFFFFFFu, ss, o);
        }
        const float mu   = s * (1.0f / DIM);
        const float var  = ss * (1.0f / DIM) - mu * mu;
        const float rstd = rsqrtf(var + LN_EPS);
        if (lane == 0) { g_mu[row] = mu; g_rs[row] = rstd; }

        #pragma unroll
        for (int i = 0; i < 8; i++) {
            const float4 g = ((const float4*)ln_g)[lane + i * 32];
            const float4 b = ((const float4*)ln_b)[lane + i * 32];
            float o[4];
            o[0] = (a[i].x - mu) * rstd * g.x + b.x;
            o[1] = (a[i].y - mu) * rstd * g.y + b.y;
            o[2] = (a[i].z - mu) * rstd * g.z + b.z;
            o[3] = (a[i].w - mu) * rstd * g.w + b.w;
            union { __half v[4]; uint2 u; } H;
            #pragma unroll
            for (int e = 0; e < 4; e++) H.v[e] = __float2half_rn(o[e]);
            ((uint2*)(g_ah + (size_t)row * DIM))[lane + i * 32] = H.u;
        }
    } else {
        const int row = blockIdx.x - LNB;
        const int c4  = t;
        float4 v = ((const float4*)(W + (size_t)row * DIM))[c4];
        float o[4] = {v.x, v.y, v.z, v.w};
        union { __half v[4]; uint2 u2; } H;
        #pragma unroll
        for (int i = 0; i < 4; i++) H.v[i] = __float2half_rn(o[i]);
        ((uint2*)(g_bext + (size_t)row * KB))[c4] = H.u2;
    }
}

// ---------------------------------------------------------------------------
// Kernel 2: persistent HMMA GEMM, BM=128 x BN=192, continuous cp.async stream.
// ---------------------------------------------------------------------------
#define ASTG_BYTES (BM * 128)
#define BSTG_BYTES (BN * 128)
#define STG_BYTES  (ASTG_BYTES + BSTG_BYTES)   // 40 KB
#define SMEM_GEMM  (STG * STG_BYTES)           // 160 KB

__device__ __forceinline__ void cp_async16(uint32_t dst, const void* src) {
    asm volatile("cp.async.cg.shared.global [%0], [%1], 16;" :: "r"(dst), "l"(src));
}
__device__ __forceinline__ void ldsm_x4(uint32_t& r0, uint32_t& r1, uint32_t& r2,
                                        uint32_t& r3, uint32_t addr) {
    asm volatile("ldmatrix.sync.aligned.m8n8.x4.shared.b16 {%0,%1,%2,%3}, [%4];"
                 : "=r"(r0), "=r"(r1), "=r"(r2), "=r"(r3) : "r"(addr));
}
__device__ __forceinline__ void mma16816(float* d, const uint32_t* a,
                                         const uint32_t* b) {
    asm volatile(
        "mma.sync.aligned.m16n8k16.row.col.f32.f16.f16.f32 "
        "{%0,%1,%2,%3}, {%4,%5,%6,%7}, {%8,%9}, {%0,%1,%2,%3};"
        : "+f"(d[0]), "+f"(d[1]), "+f"(d[2]), "+f"(d[3])
        : "r"(a[0]), "r"(a[1]), "r"(a[2]), "r"(a[3]), "r"(b[0]), "r"(b[1]));
}

__global__ void __launch_bounds__(256, 1) sru_gemm_hmma(const float* __restrict__ bias) {
    extern __shared__ char smem[];
    const uint32_t sbase = (uint32_t)__cvta_generic_to_shared(smem);
    const int tid  = threadIdx.x;
    const int lane = tid & 31;
    const int warp = tid >> 5;
    const int wm   = (warp >> 2) * 64;
    const int wn   = (warp & 3) * 48;

    auto load_stage = [&](int ltile, int lc, int buf) {
        const int lbm = (ltile >> 4) * BM;
        const int lbn = (ltile & 15) * BN;
        const uint32_t sA = sbase + buf * STG_BYTES;
        const uint32_t sB = sA + ASTG_BYTES;
        #pragma unroll
        for (int i = 0; i < 4; i++) {
            const int u = tid + i * 256;
            const int r = u >> 3, j = u & 7;
            const __half* src = g_ah + (size_t)(lbm + r) * DIM + lc * BK + j * 8;
            cp_async16(sA + r * 128 + ((j ^ (r & 7)) << 4), src);
        }
        #pragma unroll
        for (int i = 0; i < 6; i++) {
            const int u = tid + i * 256;
            const int r = u >> 3, j = u & 7;
            const __half* src = g_bext + (size_t)(lbn + r) * KB + lc * BK + j * 8;
            cp_async16(sB + r * 128 + ((j ^ (r & 7)) << 4), src);
        }
    };

    const int grid = gridDim.x;
    int tile = blockIdx.x;

    #pragma unroll
    for (int s = 0; s < 3; s++) {
        load_stage(tile, s, s);
        asm volatile("cp.async.commit_group;");
    }

    const int aRow = ((lane >> 3) & 1) * 8 + (lane & 7);
    const int aJ   = (lane >> 4);
    const int bRow = ((lane >> 4) & 1) * 8 + (lane & 7);
    const int bJ   = (lane >> 3) & 1;

    for (; tile < NTILE; tile += grid) {
        const int bm = (tile >> 4) * BM;
        const int bn = (tile & 15) * BN;

        float acc[4][6][4];
        #pragma unroll
        for (int i = 0; i < 4; i++)
            #pragma unroll
            for (int j = 0; j < 6; j++)
                #pragma unroll
                for (int e = 0; e < 4; e++) acc[i][j][e] = 0.0f;

        for (int c = 0; c < NCH; c++) {
            asm volatile("cp.async.wait_group 2;");
            __syncthreads();

            {
                int lt = tile, lc = c + 3;
                if (lc >= NCH) { lt = tile + grid; lc -= NCH; }
                if (lt < NTILE) load_stage(lt, lc, (c + 3) & 3);
            }
            asm volatile("cp.async.commit_group;");

            const int buf = c & 3;
            const uint32_t sA = sbase + buf * STG_BYTES;
            const uint32_t sB = sA + ASTG_BYTES;

            #pragma unroll
            for (int s = 0; s < 4; s++) {
                uint32_t af[4][4];
                #pragma unroll
                for (int i = 0; i < 4; i++) {
                    const int r = wm + i * 16 + aRow;
                    const int j = 2 * s + aJ;
                    ldsm_x4(af[i][0], af[i][1], af[i][2], af[i][3],
                            sA + r * 128 + ((j ^ (r & 7)) << 4));
                }
                uint32_t bf[3][4];
                #pragma unroll
                for (int p = 0; p < 3; p++) {
                    const int r = wn + p * 16 + bRow;
                    const int j = 2 * s + bJ;
                    ldsm_x4(bf[p][0], bf[p][1], bf[p][2], bf[p][3],
                            sB + r * 128 + ((j ^ (r & 7)) << 4));
                }
                #pragma unroll
                for (int i = 0; i < 4; i++)
                    #pragma unroll
                    for (int p = 0; p < 3; p++) {
                        mma16816(acc[i][2 * p],     af[i], &bf[p][0]);
                        mma16816(acc[i][2 * p + 1], af[i], &bf[p][2]);
                    }
            }
        }

        const int mrow0 = bm + wm + (lane >> 2);
        const int ncol0 = bn + wn + 2 * (lane & 3);
        #pragma unroll
        for (int j = 0; j < 6; j++) {
            const int nb = bn + wn + j * 8;
            const int n  = ncol0 + j * 8;
            const float2 b2 = *(const float2*)&bias[n];
            const bool is_u = (nb < DIM);
            #pragma unroll
            for (int i = 0; i < 4; i++) {
                const int m0 = mrow0 + i * 16;
                float v0 = acc[i][j][0] + b2.x;
                float v1 = acc[i][j][1] + b2.y;
                float v2 = acc[i][j][2] + b2.x;
                float v3 = acc[i][j][3] + b2.y;
                float2 o0, o1;
                if (is_u) { o0 = {htanh(v0), htanh(v1)};       o1 = {htanh(v2), htanh(v3)}; }
                else      { o0 = {hsigmoid(v0), hsigmoid(v1)}; o1 = {hsigmoid(v2), hsigmoid(v3)}; }
                *(__half2*)&g_ufr[(size_t)m0 * NCOLS + n]       = __floats2half2_rn(o0.x, o0.y);
                *(__half2*)&g_ufr[(size_t)(m0 + 8) * NCOLS + n] = __floats2half2_rn(o1.x, o1.y);
            }
        }
    }
}

// ---------------------------------------------------------------------------
// Kernel 3a: per-chunk (P, q); 2 lanes of d per thread (half2); SCL=32 steps
// ---------------------------------------------------------------------------
__global__ void __launch_bounds__(256) sru_scanA() {
    const int idx = blockIdx.x * 256 + threadIdx.x;   // 0..262143
    const int chunk = idx >> 12;                      // 0..63
    const int r     = idx & 4095;
    const int b     = r >> 9;
    const int dh    = r & 511;
    const int m0 = chunk * SCL * BATCH + b;

    float2 P = {1.0f, 1.0f}, q = {0.0f, 0.0f};
    #pragma unroll 4
    for (int s = 0; s < SCL; s++) {
        const size_t m = (size_t)(m0 + s * BATCH);
        const __half2* row = (const __half2*)(g_ufr + m * NCOLS);
        const float2 u = __half22float2(row[dh]);
        const float2 f = __half22float2(row[dh + DIM / 2]);
        q.x = f.x * q.x + (1.0f - f.x) * u.x;
        q.y = f.y * q.y + (1.0f - f.y) * u.y;
        P.x *= f.x;
        P.y *= f.y;
    }
    const int o = chunk * 8192 + b * DIM + 2 * dh;
    *(float2*)&g_P[o] = P;
    *(float2*)&g_q[o] = q;
}

// ---------------------------------------------------------------------------
// Kernel 3b: serial chunk combine (64 chunks, front-batched in 2 halves)
// ---------------------------------------------------------------------------
__global__ void __launch_bounds__(256) sru_scanB(const float* __restrict__ c0,
                                                 float* __restrict__ out) {
    const int idx = blockIdx.x * 256 + threadIdx.x;   // 0..8191
    float c = c0[idx];
    #pragma unroll
    for (int h = 0; h < 2; h++) {
        float P[SCH / 2], q[SCH / 2];
        #pragma unroll
        for (int k = 0; k < SCH / 2; k++) {
            const int kk = h * (SCH / 2) + k;
            P[k] = g_P[kk * 8192 + idx];
            q[k] = g_q[kk * 8192 + idx];
        }
        #pragma unroll
        for (int k = 0; k < SCH / 2; k++) {
            const int kk = h * (SCH / 2) + k;
            g_cin[kk * 8192 + idx] = c;
            c = P[k] * c + q[k];
        }
    }
    out[(size_t)MROWS * DIM + idx] = c;
}

// ---------------------------------------------------------------------------
// Kernel 3c: re-scan with true c_in (2-wide); xn from (x, mu, rstd); MUFU tanh
// ---------------------------------------------------------------------------
__global__ void __launch_bounds__(256) sru_scanC(const float* __restrict__ x,
                                                 const float* __restrict__ ln_g,
                                                 const float* __restrict__ ln_b,
                                                 float* __restrict__ out) {
    const int idx = blockIdx.x * 256 + threadIdx.x;   // 0..262143
    const int chunk = idx >> 12;
    const int r     = idx & 4095;
    const int b     = r >> 9;
    const int dh    = r & 511;
    const int m0 = chunk * SCL * BATCH + b;

    const float2 lg = ((const float2*)ln_g)[dh];
    const float2 lb = ((const float2*)ln_b)[dh];

    float2 c = *(const float2*)&g_cin[chunk * 8192 + b * DIM + 2 * dh];
    #pragma unroll 4
    for (int s = 0; s < SCL; s++) {
        const size_t m = (size_t)(m0 + s * BATCH);
        const __half2* row = (const __half2*)(g_ufr + m * NCOLS);
        const float2 u  = __half22float2(row[dh]);
        const float2 f  = __half22float2(row[dh + DIM / 2]);
        const float2 rg = __half22float2(row[dh + DIM]);
        const float2 xv = ((const float2*)(x + m * DIM))[dh];
        const float mu = g_mu[m];
        const float rs = g_rs[m];
        const float2 xn = {(xv.x - mu) * rs * lg.x + lb.x,
                           (xv.y - mu) * rs * lg.y + lb.y};
        c.x = f.x * c.x + (1.0f - f.x) * u.x;
        c.y = f.y * c.y + (1.0f - f.y) * u.y;
        float2 o;
        o.x = xv.x + rg.x * htanh(c.x) + (1.0f - rg.x) * xn.x;
        o.y = xv.y + rg.y * htanh(c.y) + (1.0f - rg.y) * xn.y;
        ((float2*)(out + m * DIM))[dh] = o;
    }
}

// ---------------------------------------------------------------------------
extern "C" void kernel_launch(void* const* d_in, const int* in_sizes, int n_in,
                              void* d_out, int out_size) {
    const float* x    = (const float*)d_in[0];
    const float* c    = (const float*)d_in[1];
    const float* W    = (const float*)d_in[2];
    const float* b    = (const float*)d_in[3];
    const float* ln_g = (const float*)d_in[4];
    const float* ln_b = (const float*)d_in[5];
    float* out = (float*)d_out;

    cudaFuncSetAttribute(sru_gemm_hmma, cudaFuncAttributeMaxDynamicSharedMemorySize,
                         SMEM_GEMM);

    int nsm = 148;
    cudaDeviceGetAttribute(&nsm, cudaDevAttrMultiProcessorCount, 0);
    if (nsm <= 0 || nsm > NTILE) nsm = 148;

    sru_prep<<<LNB + NCOLS, 256>>>(x, ln_g, ln_b, W);

    sru_gemm_hmma<<<nsm, 256, SMEM_GEMM>>>(b);

    sru_scanA<<<(SCH * BATCH * DIM / 2) / 256, 256>>>();
    sru_scanB<<<(BATCH * DIM) / 256, 256>>>(c, out);
    sru_scanC<<<(SCH * BATCH * DIM / 2) / 256, 256>>>(x, ln_g, ln_b, out);
}